// round 11
// baseline (speedup 1.0000x reference)
#include <cuda_runtime.h>

// ---------------------------------------------------------------------------
// Quantized LSTM, R6 structure (synchronous speculative barrier + inline
// tiered fixups) with a COUNTER-FREE one-RTT grid barrier:
//  - per-step record array g_rec[t][block][16]; every word is an
//    order-preserving mapped key (mapf), guaranteed nonzero -> a word's
//    presence IS its readiness flag. Blocks st.relaxed their 16 maxima and
//    poll-read all 128 records (one L2 RTT + retries); no counter, no
//    acquire/release hop, no second read.
//  - tc/hp maxima stored PER-WARP (5+5 slots) straight from each phase-C
//    warp's lane 0 -> the S2 __syncthreads is deleted (poll absorbs skew).
//  - fixups (rare, globally uniform since all blocks derive code from the
//    same records) use the old counter protocol on separate pre-zeroed cells.
// ---------------------------------------------------------------------------

#define GB       128
#define BPB      8
#define NT       640
#define T_STEPS  1024
#define NI       10
#define NH       20
#define NG       80
#define CSTRIDE  64
#define NFSLOT   4               // fallback slots/step: 0 kh-fix, 1-2 full-fix, 3 retry
#define RWORDS   16              // record words: 0-5 gates, 6-10 tc/warp, 11-15 hp/warp

__device__ __align__(128) unsigned g_ctr1[32];                       // fallback counter
__device__ __align__(64)  unsigned g_rec[T_STEPS][GB][RWORDS];       // 8MB records
__device__ unsigned g_fcells[T_STEPS * NFSLOT * CSTRIDE];            // 1MB fallback cells

__global__ void qlstm_init() {
    unsigned n1 = T_STEPS * GB * RWORDS;
    unsigned n2 = T_STEPS * NFSLOT * CSTRIDE;
    unsigned* r = &g_rec[0][0][0];
    for (unsigned i = blockIdx.x * blockDim.x + threadIdx.x; i < n1;
         i += blockDim.x * gridDim.x) r[i] = 0u;
    for (unsigned i = blockIdx.x * blockDim.x + threadIdx.x; i < n2;
         i += blockDim.x * gridDim.x) g_fcells[i] = 0u;
    if (blockIdx.x == 0 && threadIdx.x == 0) g_ctr1[0] = 0u;
}

// order-preserving float<->uint key; mapf(x) != 0 for every non-NaN x
__device__ __forceinline__ unsigned mapf(float f) {
    unsigned u = __float_as_uint(f);
    return (u & 0x80000000u) ? ~u : (u | 0x80000000u);
}
__device__ __forceinline__ float unmapf(unsigned u) {
    return __uint_as_float((u & 0x80000000u) ? (u & 0x7FFFFFFFu) : ~u);
}
__device__ __forceinline__ int po2k(float m) {
    m = fmaxf(m, 1e-8f);
    int e; float f = frexpf(m, &e);
    return (f == 0.5f) ? (e - 1) : e;
}
__device__ __forceinline__ float sc(int k)    { return __uint_as_float((unsigned)(k + 120) << 23); }
__device__ __forceinline__ float scinv(int k) { return __uint_as_float((unsigned)(134 - k) << 23); }
__device__ __forceinline__ float fq1(float x, float s, float inv) {
    float q = rintf(x * inv);
    q = fminf(fmaxf(q, -128.0f), 127.0f);
    return q * s;
}
__device__ __forceinline__ float sigm(float x) { return 1.0f / (1.0f + expf(-x)); }
__device__ __forceinline__ unsigned warp_max_u(unsigned v) {
#pragma unroll
    for (int o = 16; o; o >>= 1) v = max(v, __shfl_xor_sync(0xffffffffu, v, o));
    return v;
}
__device__ __forceinline__ void red_max_rlx(unsigned* p, unsigned v) {
    asm volatile("red.relaxed.gpu.max.u32 [%0],%1;" :: "l"(p), "r"(v) : "memory");
}
__device__ __forceinline__ void red_add_rel(unsigned* p, unsigned v) {
    asm volatile("red.release.gpu.add.u32 [%0],%1;" :: "l"(p), "r"(v) : "memory");
}
__device__ __forceinline__ unsigned ld_acq(const unsigned* p) {
    unsigned v; asm volatile("ld.acquire.gpu.u32 %0,[%1];" : "=r"(v) : "l"(p) : "memory"); return v;
}
__device__ __forceinline__ unsigned ld_rlx(const unsigned* p) {
    unsigned v; asm volatile("ld.relaxed.gpu.u32 %0,[%1];" : "=r"(v) : "l"(p) : "memory"); return v;
}
__device__ __forceinline__ void st_rlx(unsigned* p, unsigned v) {
    asm volatile("st.relaxed.gpu.u32 [%0],%1;" :: "l"(p), "r"(v) : "memory");
}
__device__ __forceinline__ uint4 ld_rlx4(const unsigned* p) {
    uint4 v;
    asm volatile("ld.relaxed.gpu.v4.b32 {%0,%1,%2,%3},[%4];"
                 : "=r"(v.x), "=r"(v.y), "=r"(v.z), "=r"(v.w) : "l"(p) : "memory");
    return v;
}

// rare-path synchronous round on cumulative counter g_ctr1
__device__ __forceinline__ unsigned grid_round1(unsigned* cell0, unsigned myv, int nc,
                                                unsigned tgt, int lane) {
    if (lane < nc) red_max_rlx(cell0 + lane * CSTRIDE, myv);
    __syncwarp();
    if (lane == 0) red_add_rel(&g_ctr1[0], 1u);
    if (lane < nc) { while (ld_acq(&g_ctr1[0]) < tgt) { } }
    __syncwarp();
    return (lane < nc) ? ld_rlx(cell0 + lane * CSTRIDE) : 0u;
}

__global__ void __launch_bounds__(NT, 1) qlstm_main(
    const float* __restrict__ x,
    const float* __restrict__ Wih,
    const float* __restrict__ Whh,
    float* __restrict__ out)
{
    __shared__ __align__(16) float sh_h[BPB * NH];
    __shared__ __align__(16) float sh_x[BPB * NI];
    __shared__ float               sh_act[NG * BPB];
    __shared__ unsigned            sh_red[12];
    __shared__ int                 sh_k[8];    // 0:k1 1-4:ka 5:k3 6:kh 7:code (true values)
    __shared__ int                 sh_kp[6];   // predictions: k1, ka0-3, k3

    const int tid  = threadIdx.x;
    const int bid  = blockIdx.x;
    const int g    = tid / BPB;
    const int b    = tid % BPB;
    const int gr   = tid / 160;          // warp-uniform gate group
    const int lane = tid & 31;
    const int wid  = tid >> 5;

    if (tid < 12) sh_red[tid] = 0u;
    if (tid < 6)  sh_kp[tid] = 99;       // garbage -> full miss at t=0
    if (tid < 8)  sh_k[tid] = 0;
    if (tid < BPB * NH) sh_h[tid] = 0.0f;
    __syncthreads();

    // ---- weight scale (block-local, once) ----
    {
        float wm = 0.0f;
        for (int k = tid; k < NG * NI; k += NT) wm = fmaxf(wm, fabsf(Wih[k]));
        for (int k = tid; k < NG * NH; k += NT) wm = fmaxf(wm, fabsf(Whh[k]));
        unsigned u = warp_max_u(__float_as_uint(wm));
        if (lane == 0) atomicMax(&sh_red[11], u);
        __syncthreads();
    }
    int kw = po2k(__uint_as_float(sh_red[11]));
    float ws = sc(kw), wsi = scinv(kw);
    __syncthreads();
    if (tid == 0) sh_red[11] = 0u;
    __syncthreads();

    float wi[NI], wh[NH];
#pragma unroll
    for (int i2 = 0; i2 < NI; i2++) wi[i2] = fq1(Wih[g * NI + i2], ws, wsi);
#pragma unroll
    for (int j2 = 0; j2 < NH; j2++) wh[j2] = fq1(Whh[g * NH + j2], ws, wsi);

    float    c = 0.0f, c_prev = 0.0f;
    float    tc = 0.0f, oq = 0.0f, hp = 0.0f;
    unsigned nbar1 = 0;

    const int sq  = tid - 560;           // warps 17-19 stage x
    const int sxb = (sq >= 0) ? sq / NI : 0;
    const int sxi = (sq >= 0) ? sq % NI : 0;
    float xr = 0.0f;
    if (sq >= 0) {
        sh_x[sq] = x[((size_t)(bid * BPB + sxb) * T_STEPS + 0) * NI + sxi];
        xr       = x[((size_t)(bid * BPB + sxb) * T_STEPS + 1) * NI + sxi];
    }
    __syncthreads();

    for (int t = 0; t < T_STEPS; ++t) {
        const int k1p = sh_kp[0], kap = sh_kp[1 + gr], k3p = sh_kp[5];

        // ===== phase B: pre + group signed extrema + speculative activations =====
        float p0 = 0.0f, p1 = 0.0f;
        {
            const float2* px = reinterpret_cast<const float2*>(&sh_x[b * NI]);
            const float2* ph = reinterpret_cast<const float2*>(&sh_h[b * NH]);
#pragma unroll
            for (int j = 0; j < NI / 2; j++) {
                float2 v = px[j];
                p0 = fmaf(v.x, wi[2 * j], p0); p1 = fmaf(v.y, wi[2 * j + 1], p1);
            }
#pragma unroll
            for (int j = 0; j < NH / 2; j++) {
                float2 v = ph[j];
                p0 = fmaf(v.x, wh[2 * j], p0); p1 = fmaf(v.y, wh[2 * j + 1], p1);
            }
        }
        float pre = p0 + p1;
        unsigned kp = warp_max_u(mapf(pre));
        unsigned kn = warp_max_u(mapf(-pre));
        if (lane == 0) { atomicMax(&sh_red[gr], kp); atomicMax(&sh_red[4 + gr], kn); }
        {
            float gq  = fq1(pre, sc(k1p), scinv(k1p));
            float act = (gr == 2) ? tanhf(gq) : sigm(gq);
            sh_act[tid] = fq1(act, sc(kap), scinv(kap));
        }
        __syncthreads();                                        // S1
        if (sq >= 0 && t + 1 < T_STEPS) sh_x[sq] = xr;

        unsigned* rec = &g_rec[t][bid][0];

        // ===== wid0: gather gate extrema, fire record words 0-5 =====
        if (wid == 0) {
            unsigned v = (lane < 8) ? sh_red[lane] : 0u;
            __syncwarp();
            if (lane < 8) sh_red[lane] = 0u;
            unsigned n0 = __shfl_sync(0xffffffffu, v, 4);
            unsigned n1 = __shfl_sync(0xffffffffu, v, 5);
            unsigned n2 = __shfl_sync(0xffffffffu, v, 6);
            unsigned n3 = __shfl_sync(0xffffffffu, v, 7);
            unsigned myv = v;
            if (lane == 4) myv = n2;                            // max(-pre) tanh group
            if (lane == 5) myv = max(max(n0, n1), max(n2, n3)); // global max(-pre)
            if (lane < 6) st_rlx(rec + lane, myv);
        }

        // ===== phase C: c update, tanh, speculative h_pre; per-warp fire =====
        tc = 0.0f; hp = 0.0f;
        if (tid < 160) {
            float iq = sh_act[tid], ff = sh_act[tid + 160], gg = sh_act[tid + 320];
            oq = sh_act[tid + 480];
            c_prev = c;
            c  = ff * c + iq * gg;
            tc = tanhf(c);
            hp = oq * fq1(tc, sc(k3p), scinv(k3p));
        }
        if (wid < 5) {
            unsigned a1 = warp_max_u(mapf(fabsf(tc)));
            unsigned a2 = warp_max_u(mapf(fabsf(hp)));
            if (lane == 0) { st_rlx(rec + 6 + wid, a1); st_rlx(rec + 11 + wid, a2); }
        }
        if (sq >= 0 && t + 2 < T_STEPS)
            xr = x[((size_t)(bid * BPB + sxb) * T_STEPS + (t + 2)) * NI + sxi];

        // ===== counter-free barrier: poll-read all 128 records, reduce, verify =====
        if (wid == 0) {
            unsigned m[RWORDS];
#pragma unroll
            for (int j = 0; j < RWORDS; j++) m[j] = 0u;
            unsigned done = 0u;
            const unsigned* rb = &g_rec[t][0][0];
            while (done != 0xFu) {
#pragma unroll
                for (int k = 0; k < 4; k++) {
                    if (done & (1u << k)) continue;
                    const unsigned* rp = rb + (unsigned)(lane * 4 + k) * RWORDS;
                    uint4 q0 = ld_rlx4(rp);
                    uint4 q1 = ld_rlx4(rp + 4);
                    uint4 q2 = ld_rlx4(rp + 8);
                    uint4 q3 = ld_rlx4(rp + 12);
                    bool ok = q0.x && q0.y && q0.z && q0.w &&
                              q1.x && q1.y && q1.z && q1.w &&
                              q2.x && q2.y && q2.z && q2.w &&
                              q3.x && q3.y && q3.z && q3.w;
                    if (ok) {
                        m[0] = max(m[0], q0.x);  m[1] = max(m[1], q0.y);
                        m[2] = max(m[2], q0.z);  m[3] = max(m[3], q0.w);
                        m[4] = max(m[4], q1.x);  m[5] = max(m[5], q1.y);
                        m[6] = max(m[6], q1.z);  m[7] = max(m[7], q1.w);
                        m[8] = max(m[8], q2.x);  m[9] = max(m[9], q2.y);
                        m[10] = max(m[10], q2.z); m[11] = max(m[11], q2.w);
                        m[12] = max(m[12], q3.x); m[13] = max(m[13], q3.y);
                        m[14] = max(m[14], q3.z); m[15] = max(m[15], q3.w);
                        done |= 1u << k;
                    }
                }
            }
#pragma unroll
            for (int o = 16; o; o >>= 1) {
#pragma unroll
                for (int j = 0; j < RWORDS; j++)
                    m[j] = max(m[j], __shfl_xor_sync(0xffffffffu, m[j], o));
            }
            unsigned tck = max(max(m[6], m[7]), max(max(m[8], m[9]), m[10]));
            unsigned hpk = max(max(m[11], m[12]), max(max(m[13], m[14]), m[15]));
            float maxpre = unmapf(max(max(m[0], m[1]), max(m[2], m[3])));
            int k1 = po2k(fmaxf(maxpre, unmapf(m[5])));
            float s1 = sc(k1), v1 = scinv(k1);
            float a;
            if (lane == 2) {
                float q1f = fq1(unmapf(m[2]), s1, v1);
                float q2f = fq1(-unmapf(m[4]), s1, v1);
                a = tanhf(fmaxf(q1f, -q2f));
            } else {
                a = sigm(fq1(unmapf(m[lane < 3 ? lane : 3]), s1, v1));
            }
            int ka  = po2k(fabsf(a));
            int k3t = po2k(unmapf(tck));
            int kht = po2k(unmapf(hpk));
            bool okl = (lane < 4) ? (ka == sh_kp[1 + lane]) : true;
            unsigned bm = __ballot_sync(0xffffffffu, okl);
            int hit1 = (((bm & 0xFu) == 0xFu) && (k1 == sh_kp[0])) ? 1 : 0;
            int hit3 = (k3t == sh_kp[5]) ? 1 : 0;
            int code = hit1 ? (hit3 ? 0 : 1) : 2;
            if (lane < 4) { sh_k[1 + lane] = ka; sh_kp[1 + lane] = ka; }
            if (lane == 0) {
                sh_k[0] = k1; sh_kp[0] = k1;
                if (hit1) { sh_k[5] = k3t; sh_kp[5] = k3t; }
                if (hit1 && hit3) sh_k[6] = kht;
                sh_k[7] = code;
            }
        }
        __syncthreads();                                        // S3

        const int code = sh_k[7];
        unsigned* fc = &g_fcells[(size_t)t * NFSLOT * CSTRIDE];

        if (code == 1) {
            // k3 miss (tc exact): recompute hp with true k3, one round for kh
            float s3 = sc(sh_k[5]), v3 = scinv(sh_k[5]);
            if (tid < 160) hp = oq * fq1(tc, s3, v3);
            if (wid < 5) {
                unsigned a2 = warp_max_u(__float_as_uint(fabsf(hp)));
                if (lane == 0) atomicMax(&sh_red[10], a2);
            }
            __syncthreads();
            if (wid == 0) {
                unsigned v = (lane == 0) ? sh_red[10] : 0u;
                __syncwarp();
                if (lane == 0) sh_red[10] = 0u;
                nbar1++;
                unsigned cv = grid_round1(fc, v, 1, nbar1 * GB, lane);
                if (lane == 0) sh_k[6] = po2k(__uint_as_float(cv));
            }
            __syncthreads();
        } else if (code == 2) {
            // full miss: replay with true k1/ka from records
            {
                int k1 = sh_k[0], kat = sh_k[1 + gr];
                float gq  = fq1(pre, sc(k1), scinv(k1));
                float act = (gr == 2) ? tanhf(gq) : sigm(gq);
                sh_act[tid] = fq1(act, sc(kat), scinv(kat));
            }
            __syncthreads();
            int k3g = sh_kp[5];
            if (tid < 160) {
                float iq = sh_act[tid], ff = sh_act[tid + 160], gg = sh_act[tid + 320];
                oq = sh_act[tid + 480];
                c  = ff * c_prev + iq * gg;
                tc = tanhf(c);
                hp = oq * fq1(tc, sc(k3g), scinv(k3g));
            }
            if (wid < 5) {
                unsigned a1 = warp_max_u(__float_as_uint(fabsf(tc)));
                unsigned a2 = warp_max_u(__float_as_uint(fabsf(hp)));
                if (lane == 0) { atomicMax(&sh_red[10], a1); atomicMax(&sh_red[11], a2); }
            }
            __syncthreads();
            if (wid == 0) {
                unsigned v = (lane < 2) ? sh_red[10 + lane] : 0u;
                __syncwarp();
                if (lane < 2) sh_red[10 + lane] = 0u;
                nbar1++;
                unsigned cv = grid_round1(fc + 1 * CSTRIDE, v, 2, nbar1 * GB, lane);
                int kx = po2k(__uint_as_float(cv));
                int k3 = __shfl_sync(0xffffffffu, kx, 0);
                int kh = __shfl_sync(0xffffffffu, kx, 1);
                if (lane == 0) {
                    sh_k[5] = k3; sh_kp[5] = k3; sh_k[6] = kh;
                    sh_k[7] = (k3 == k3g) ? 0 : 1;   // retry flag
                }
            }
            __syncthreads();
            if (sh_k[7]) {                           // k3 guess also missed
                float s3 = sc(sh_k[5]), v3 = scinv(sh_k[5]);
                if (tid < 160) hp = oq * fq1(tc, s3, v3);
                if (wid < 5) {
                    unsigned a2 = warp_max_u(__float_as_uint(fabsf(hp)));
                    if (lane == 0) atomicMax(&sh_red[10], a2);
                }
                __syncthreads();
                if (wid == 0) {
                    unsigned v = (lane == 0) ? sh_red[10] : 0u;
                    __syncwarp();
                    if (lane == 0) sh_red[10] = 0u;
                    nbar1++;
                    unsigned cv = grid_round1(fc + 3 * CSTRIDE, v, 1, nbar1 * GB, lane);
                    if (lane == 0) sh_k[6] = po2k(__uint_as_float(cv));
                }
                __syncthreads();
            }
        }

        // ===== h quantize, publish, output =====
        if (tid < 160) {
            int kh = sh_k[6];
            float hq = fq1(hp, sc(kh), scinv(kh));
            sh_h[b * NH + g] = hq;
            out[((size_t)(bid * BPB + b) * T_STEPS + t) * NH + g] = hq;
        }
        __syncthreads();                                        // S4
    }
}

extern "C" void kernel_launch(void* const* d_in, const int* in_sizes, int n_in,
                              void* d_out, int out_size) {
    (void)in_sizes; (void)n_in; (void)out_size;
    qlstm_init<<<256, 512>>>();
    qlstm_main<<<GB, NT>>>((const float*)d_in[0],
                           (const float*)d_in[1],
                           (const float*)d_in[2],
                           (float*)d_out);
}

// round 12
// speedup vs baseline: 1.4915x; 1.4915x over previous
#include <cuda_runtime.h>

// ---------------------------------------------------------------------------
// Quantized LSTM — R6 structure (single synchronous speculative grid barrier
// per step, red.max cells + acq_rel counter) with the post-barrier work
// removed from the hit path:
//  - h/out written SPECULATIVELY in phase C using predicted kh (cell 7
//    verifies it; exact whenever k1/ka/k3 all hit). Full-hit steps do
//    nothing after the barrier but __syncthreads.
//  - kh-only miss = local rewrite (cell 7 exact, no extra grid round).
//  - S2 replaced by bar.sync(1,160): only warps 0-4 rendezvous before the
//    fire; warps 5-19 wait at S3, overlapping the poll.
//  - gate cells (0-5) fired right after S1, overlapping phase C.
// ---------------------------------------------------------------------------

#define GB       128
#define BPB      8
#define NT       640
#define T_STEPS  1024
#define NI       10
#define NH       20
#define NG       80
#define CSTRIDE  64              // 256B between cells
#define NCELL    16              // 0-7 main, 8 kh-fix, 9-10 full-fix, 11 retry

__device__ __align__(128) unsigned g_ctr0[32];
__device__ unsigned g_cells[T_STEPS * NCELL * CSTRIDE];

__global__ void qlstm_init() {
    int i = blockIdx.x * blockDim.x + threadIdx.x;   // 16384 = T_STEPS*NCELL
    if (i == 0) g_ctr0[0] = 0u;
    if (i < T_STEPS * NCELL) g_cells[i * CSTRIDE] = 0u;
}

__device__ __forceinline__ unsigned mapf(float f) {
    unsigned u = __float_as_uint(f);
    return (u & 0x80000000u) ? ~u : (u | 0x80000000u);
}
__device__ __forceinline__ float unmapf(unsigned u) {
    return __uint_as_float((u & 0x80000000u) ? (u & 0x7FFFFFFFu) : ~u);
}
__device__ __forceinline__ int po2k(float m) {
    m = fmaxf(m, 1e-8f);
    int e; float f = frexpf(m, &e);
    return (f == 0.5f) ? (e - 1) : e;
}
__device__ __forceinline__ float sc(int k)    { return __uint_as_float((unsigned)(k + 120) << 23); }
__device__ __forceinline__ float scinv(int k) { return __uint_as_float((unsigned)(134 - k) << 23); }
__device__ __forceinline__ float fq1(float x, float s, float inv) {
    float q = rintf(x * inv);
    q = fminf(fmaxf(q, -128.0f), 127.0f);
    return q * s;
}
__device__ __forceinline__ float sigm(float x) { return 1.0f / (1.0f + expf(-x)); }
__device__ __forceinline__ unsigned warp_max_u(unsigned v) {
#pragma unroll
    for (int o = 16; o; o >>= 1) v = max(v, __shfl_xor_sync(0xffffffffu, v, o));
    return v;
}
__device__ __forceinline__ void red_max_rlx(unsigned* p, unsigned v) {
    asm volatile("red.relaxed.gpu.max.u32 [%0],%1;" :: "l"(p), "r"(v) : "memory");
}
__device__ __forceinline__ unsigned atom_add_acqrel(unsigned* p, unsigned v) {
    unsigned old;
    asm volatile("atom.acq_rel.gpu.add.u32 %0,[%1],%2;" : "=r"(old) : "l"(p), "r"(v) : "memory");
    return old;
}
__device__ __forceinline__ unsigned ld_acq(const unsigned* p) {
    unsigned v; asm volatile("ld.acquire.gpu.u32 %0,[%1];" : "=r"(v) : "l"(p) : "memory"); return v;
}
__device__ __forceinline__ unsigned ld_rlx(const unsigned* p) {
    unsigned v; asm volatile("ld.relaxed.gpu.u32 %0,[%1];" : "=r"(v) : "l"(p) : "memory"); return v;
}

// fallback grid round (rare path), R6-proven protocol
__device__ __forceinline__ unsigned grid_bar(unsigned* cell0, unsigned myv, int nc,
                                             unsigned tgt, int lane) {
    if (lane < nc) red_max_rlx(cell0 + lane * CSTRIDE, myv);
    __syncwarp();
    unsigned last = 0;
    if (lane == 0) last = (atom_add_acqrel(&g_ctr0[0], 1u) == tgt - 1u) ? 1u : 0u;
    last = __shfl_sync(0xffffffffu, last, 0);
    if (!last) { while (ld_acq(&g_ctr0[0]) < tgt) { } }
    __syncwarp();
    return (lane < nc) ? ld_rlx(cell0 + lane * CSTRIDE) : 0u;
}

__global__ void __launch_bounds__(NT, 1) qlstm_main(
    const float* __restrict__ x,
    const float* __restrict__ Wih,
    const float* __restrict__ Whh,
    float* __restrict__ out)
{
    __shared__ __align__(16) float sh_h[BPB * NH];
    __shared__ __align__(16) float sh_x[BPB * NI];
    __shared__ float               sh_act[NG * BPB];
    __shared__ unsigned            sh_red[12];
    __shared__ int                 sh_k[8];    // true: 0:k1 1-4:ka 5:k3 6:kh 7:code
    __shared__ int                 sh_kp[8];   // predictions: k1, ka0-3, k3, kh

    const int tid  = threadIdx.x;
    const int bid  = blockIdx.x;
    const int g    = tid / BPB;
    const int b    = tid % BPB;
    const int gr   = tid / 160;          // warp-uniform gate group
    const int lane = tid & 31;
    const int wid  = tid >> 5;

    if (tid < 12) sh_red[tid] = 0u;
    if (tid < 8)  { sh_kp[tid] = 99; sh_k[tid] = 0; }   // garbage -> full miss at t=0
    if (tid < BPB * NH) sh_h[tid] = 0.0f;
    __syncthreads();

    // ---- weight scale (block-local, once) ----
    {
        float wm = 0.0f;
        for (int k = tid; k < NG * NI; k += NT) wm = fmaxf(wm, fabsf(Wih[k]));
        for (int k = tid; k < NG * NH; k += NT) wm = fmaxf(wm, fabsf(Whh[k]));
        unsigned u = warp_max_u(__float_as_uint(wm));
        if (lane == 0) atomicMax(&sh_red[11], u);
        __syncthreads();
    }
    int kw = po2k(__uint_as_float(sh_red[11]));
    float ws = sc(kw), wsi = scinv(kw);
    __syncthreads();
    if (tid == 0) sh_red[11] = 0u;
    __syncthreads();

    float wi[NI], wh[NH];
#pragma unroll
    for (int i2 = 0; i2 < NI; i2++) wi[i2] = fq1(Wih[g * NI + i2], ws, wsi);
#pragma unroll
    for (int j2 = 0; j2 < NH; j2++) wh[j2] = fq1(Whh[g * NH + j2], ws, wsi);

    float    c = 0.0f, c_prev = 0.0f;
    float    tc = 0.0f, oq = 0.0f, hp = 0.0f;
    unsigned nbar = 0;

    const int sq  = tid - 560;           // warps 17-19 stage x
    const int sxb = (sq >= 0) ? sq / NI : 0;
    const int sxi = (sq >= 0) ? sq % NI : 0;
    float xr = 0.0f;
    if (sq >= 0) {
        sh_x[sq] = x[((size_t)(bid * BPB + sxb) * T_STEPS + 0) * NI + sxi];
        xr       = x[((size_t)(bid * BPB + sxb) * T_STEPS + 1) * NI + sxi];
    }
    __syncthreads();

    for (int t = 0; t < T_STEPS; ++t) {
        const int k1p = sh_kp[0], kap = sh_kp[1 + gr], k3p = sh_kp[5], khp = sh_kp[6];
        unsigned* cb = &g_cells[(size_t)t * NCELL * CSTRIDE];

        // ===== phase B: pre + gate group extrema + speculative activations =====
        float p0 = 0.0f, p1 = 0.0f;
        {
            const float2* px = reinterpret_cast<const float2*>(&sh_x[b * NI]);
            const float2* ph = reinterpret_cast<const float2*>(&sh_h[b * NH]);
#pragma unroll
            for (int j = 0; j < NI / 2; j++) {
                float2 v = px[j];
                p0 = fmaf(v.x, wi[2 * j], p0); p1 = fmaf(v.y, wi[2 * j + 1], p1);
            }
#pragma unroll
            for (int j = 0; j < NH / 2; j++) {
                float2 v = ph[j];
                p0 = fmaf(v.x, wh[2 * j], p0); p1 = fmaf(v.y, wh[2 * j + 1], p1);
            }
        }
        float pre = p0 + p1;
        unsigned kp = warp_max_u(mapf(pre));
        unsigned kn = warp_max_u(mapf(-pre));
        if (lane == 0) { atomicMax(&sh_red[gr], kp); atomicMax(&sh_red[4 + gr], kn); }
        {
            float gq  = fq1(pre, sc(k1p), scinv(k1p));
            float act = (gr == 2) ? tanhf(gq) : sigm(gq);
            sh_act[tid] = fq1(act, sc(kap), scinv(kap));
        }
        __syncthreads();                                        // S1

        // ===== warp0: early fire of gate cells 0-5 (overlaps phase C) =====
        if (wid == 0) {
            unsigned v = (lane < 8) ? sh_red[lane] : 0u;
            __syncwarp();
            if (lane < 8) sh_red[lane] = 0u;
            unsigned n0 = __shfl_sync(0xffffffffu, v, 4);
            unsigned n1 = __shfl_sync(0xffffffffu, v, 5);
            unsigned n2 = __shfl_sync(0xffffffffu, v, 6);
            unsigned n3 = __shfl_sync(0xffffffffu, v, 7);
            unsigned myv = v;
            if (lane == 4) myv = n2;                            // max(-pre) tanh group
            if (lane == 5) myv = max(max(n0, n1), max(n2, n3)); // global max(-pre)
            if (lane < 6) red_max_rlx(cb + lane * CSTRIDE, myv);
        }
        if (sq >= 0 && t + 1 < T_STEPS) sh_x[sq] = xr;

        // ===== phase C (warps 0-4): c, tanh, speculative h_pre AND h =====
        tc = 0.0f; hp = 0.0f;
        if (tid < 160) {
            float iq = sh_act[tid], ff = sh_act[tid + 160], gg = sh_act[tid + 320];
            oq = sh_act[tid + 480];
            c_prev = c;
            c  = ff * c + iq * gg;
            tc = tanhf(c);
            hp = oq * fq1(tc, sc(k3p), scinv(k3p));
            float hq = fq1(hp, sc(khp), scinv(khp));            // speculative h
            sh_h[b * NH + g] = hq;
            out[((size_t)(bid * BPB + b) * T_STEPS + t) * NH + g] = hq;
            unsigned a1 = warp_max_u(__float_as_uint(fabsf(tc)));
            unsigned a2 = warp_max_u(__float_as_uint(fabsf(hp)));
            if (lane == 0) { atomicMax(&sh_red[8], a1); atomicMax(&sh_red[9], a2); }
            asm volatile("bar.sync 1, 160;" ::: "memory");      // warps 0-4 only
        }
        if (sq >= 0 && t + 2 < T_STEPS)
            xr = x[((size_t)(bid * BPB + sxb) * T_STEPS + (t + 2)) * NI + sxi];

        // ===== warp0: fire cells 6-7 + counter, poll, read, verify =====
        if (wid == 0) {
            unsigned v89 = (lane < 2) ? sh_red[8 + lane] : 0u;
            __syncwarp();
            if (lane < 2) sh_red[8 + lane] = 0u;
            unsigned t8 = __shfl_sync(0xffffffffu, v89, 0);
            unsigned t9 = __shfl_sync(0xffffffffu, v89, 1);
            if (lane == 6) red_max_rlx(cb + 6 * CSTRIDE, t8);
            if (lane == 7) red_max_rlx(cb + 7 * CSTRIDE, t9);
            __syncwarp();
            nbar++;
            unsigned tgt = nbar * GB, last = 0;
            if (lane == 0) last = (atom_add_acqrel(&g_ctr0[0], 1u) == tgt - 1u) ? 1u : 0u;
            last = __shfl_sync(0xffffffffu, last, 0);
            if (!last) { while (ld_acq(&g_ctr0[0]) < tgt) { } }
            __syncwarp();
            unsigned cv = (lane < 8) ? ld_rlx(cb + lane * CSTRIDE) : 0u;

            unsigned kk = (lane < 4 || lane == 5) ? cv : 0u;
            kk = max(kk, __shfl_xor_sync(0xffffffffu, kk, 4));
            kk = max(kk, __shfl_xor_sync(0xffffffffu, kk, 2));
            kk = max(kk, __shfl_xor_sync(0xffffffffu, kk, 1));
            int k1 = po2k(unmapf(kk));
            float s1 = sc(k1), v1 = scinv(k1);
            float mng = unmapf(__shfl_sync(0xffffffffu, cv, 4));
            float myp = unmapf(cv);
            float a;
            if (lane == 2) {
                float q1 = fq1(myp, s1, v1), q2 = fq1(-mng, s1, v1);
                a = tanhf(fmaxf(q1, -q2));
            } else {
                a = sigm(fq1(myp, s1, v1));
            }
            int ka  = po2k(fabsf(a));
            int k3t = po2k(__uint_as_float(__shfl_sync(0xffffffffu, cv, 6)));
            int kht = po2k(__uint_as_float(__shfl_sync(0xffffffffu, cv, 7)));
            bool okl = (lane < 4) ? (ka == sh_kp[1 + lane]) : true;
            unsigned bm = __ballot_sync(0xffffffffu, okl);
            int hit1 = (((bm & 0xFu) == 0xFu) && (k1 == sh_kp[0])) ? 1 : 0;
            int hit3 = (k3t == sh_kp[5]) ? 1 : 0;
            int hith = (kht == sh_kp[6]) ? 1 : 0;
            int code = hit1 ? (hit3 ? (hith ? 0 : 1) : 2) : 3;
            if (lane < 4) { sh_k[1 + lane] = ka; sh_kp[1 + lane] = ka; }
            if (lane == 0) {
                sh_k[0] = k1; sh_kp[0] = k1;
                if (hit1) { sh_k[5] = k3t; sh_kp[5] = k3t; }
                if (hit1 && hit3) { sh_k[6] = kht; sh_kp[6] = kht; }
                sh_k[7] = code;
            }
        }
        __syncthreads();                                        // S3

        const int code = sh_k[7];
        if (code == 0) continue;                                // full hit: done

        if (code == 1) {
            // kh miss only (cell 7 exact): local rewrite
            if (tid < 160) {
                float sh_ = sc(sh_k[6]), vh_ = scinv(sh_k[6]);
                float hq = fq1(hp, sh_, vh_);
                sh_h[b * NH + g] = hq;
                out[((size_t)(bid * BPB + b) * T_STEPS + t) * NH + g] = hq;
            }
            __syncthreads();
        } else if (code == 2) {
            // k3 miss (tc exact): recompute hp with true k3, one round for kh
            float s3 = sc(sh_k[5]), v3 = scinv(sh_k[5]);
            if (tid < 160) hp = oq * fq1(tc, s3, v3);
            if (wid < 5) {
                unsigned a2 = warp_max_u(__float_as_uint(fabsf(hp)));
                if (lane == 0) atomicMax(&sh_red[10], a2);
            }
            __syncthreads();
            if (wid == 0) {
                unsigned v = (lane == 0) ? sh_red[10] : 0u;
                __syncwarp();
                if (lane == 0) sh_red[10] = 0u;
                nbar++;
                unsigned cv = grid_bar(cb + 8 * CSTRIDE, v, 1, nbar * GB, lane);
                if (lane == 0) { sh_k[6] = po2k(__uint_as_float(cv)); sh_kp[6] = sh_k[6]; }
            }
            __syncthreads();
            if (tid < 160) {
                float sh_ = sc(sh_k[6]), vh_ = scinv(sh_k[6]);
                float hq = fq1(hp, sh_, vh_);
                sh_h[b * NH + g] = hq;
                out[((size_t)(bid * BPB + b) * T_STEPS + t) * NH + g] = hq;
            }
            __syncthreads();
        } else {
            // full miss: replay from exact pre / c_prev with true k1/ka
            {
                int k1 = sh_k[0], kat = sh_k[1 + gr];
                float gq  = fq1(pre, sc(k1), scinv(k1));
                float act = (gr == 2) ? tanhf(gq) : sigm(gq);
                sh_act[tid] = fq1(act, sc(kat), scinv(kat));
            }
            __syncthreads();
            int k3g = sh_kp[5];
            if (tid < 160) {
                float iq = sh_act[tid], ff = sh_act[tid + 160], gg = sh_act[tid + 320];
                oq = sh_act[tid + 480];
                c  = ff * c_prev + iq * gg;
                tc = tanhf(c);
                hp = oq * fq1(tc, sc(k3g), scinv(k3g));
            }
            if (wid < 5) {
                unsigned a1 = warp_max_u(__float_as_uint(fabsf(tc)));
                unsigned a2 = warp_max_u(__float_as_uint(fabsf(hp)));
                if (lane == 0) { atomicMax(&sh_red[10], a1); atomicMax(&sh_red[11], a2); }
            }
            __syncthreads();
            if (wid == 0) {
                unsigned v = (lane < 2) ? sh_red[10 + lane] : 0u;
                __syncwarp();
                if (lane < 2) sh_red[10 + lane] = 0u;
                nbar++;
                unsigned cv = grid_bar(cb + 9 * CSTRIDE, v, 2, nbar * GB, lane);
                int kx = po2k(__uint_as_float(cv));
                int k3 = __shfl_sync(0xffffffffu, kx, 0);
                int kh = __shfl_sync(0xffffffffu, kx, 1);
                if (lane == 0) {
                    sh_k[5] = k3; sh_kp[5] = k3; sh_k[6] = kh; sh_kp[6] = kh;
                    sh_k[7] = (k3 == k3g) ? 0 : 1;   // retry flag
                }
            }
            __syncthreads();
            if (sh_k[7]) {                           // k3 guess also missed
                float s3 = sc(sh_k[5]), v3 = scinv(sh_k[5]);
                if (tid < 160) hp = oq * fq1(tc, s3, v3);
                if (wid < 5) {
                    unsigned a2 = warp_max_u(__float_as_uint(fabsf(hp)));
                    if (lane == 0) atomicMax(&sh_red[10], a2);
                }
                __syncthreads();
                if (wid == 0) {
                    unsigned v = (lane == 0) ? sh_red[10] : 0u;
                    __syncwarp();
                    if (lane == 0) sh_red[10] = 0u;
                    nbar++;
                    unsigned cv = grid_bar(cb + 11 * CSTRIDE, v, 1, nbar * GB, lane);
                    if (lane == 0) { sh_k[6] = po2k(__uint_as_float(cv)); sh_kp[6] = sh_k[6]; }
                }
                __syncthreads();
            }
            if (tid < 160) {
                float sh_ = sc(sh_k[6]), vh_ = scinv(sh_k[6]);
                float hq = fq1(hp, sh_, vh_);
                sh_h[b * NH + g] = hq;
                out[((size_t)(bid * BPB + b) * T_STEPS + t) * NH + g] = hq;
            }
            __syncthreads();
        }
    }
}

extern "C" void kernel_launch(void* const* d_in, const int* in_sizes, int n_in,
                              void* d_out, int out_size) {
    (void)in_sizes; (void)n_in; (void)out_size;
    qlstm_init<<<32, 512>>>();
    qlstm_main<<<GB, NT>>>((const float*)d_in[0],
                           (const float*)d_in[1],
                           (const float*)d_in[2],
                           (float*)d_out);
}

// round 13
// speedup vs baseline: 1.5335x; 1.0281x over previous
#include <cuda_runtime.h>

// ---------------------------------------------------------------------------
// Quantized LSTM — R6 barrier (red.max cells + acq_rel counter, synchronous
// verify, tiered fixups) with ROLE SEPARATION:
//   warp 0     : barrier warp only (gather, fire, poll, verify)
//   warps 5-9  : phase C (c/tanh/h state) + speculative h/out store
//   warps 1-19 : phase B gate rows; warps 17-19 also stage x
// Speculative h uses predicted kh (verified by cell 7); full-hit steps do
// nothing after the barrier. bar.sync(1,192) syncs only {w0, w5-9} before the
// counter fire; other warps wait at S3, overlapping the poll.
// ---------------------------------------------------------------------------

#define GB       128
#define BPB      8
#define NT       640
#define T_STEPS  1024
#define NI       10
#define NH       20
#define NG       80
#define CSTRIDE  64              // 256B between cells
#define NCELL    16              // 0-7 main, 8 kh-fix, 9-10 full-fix, 11 retry

__device__ __align__(128) unsigned g_ctr0[32];
__device__ unsigned g_cells[T_STEPS * NCELL * CSTRIDE];

__global__ void qlstm_init() {
    int i = blockIdx.x * blockDim.x + threadIdx.x;   // 16384 = T_STEPS*NCELL
    if (i == 0) g_ctr0[0] = 0u;
    if (i < T_STEPS * NCELL) g_cells[i * CSTRIDE] = 0u;
}

__device__ __forceinline__ unsigned mapf(float f) {
    unsigned u = __float_as_uint(f);
    return (u & 0x80000000u) ? ~u : (u | 0x80000000u);
}
__device__ __forceinline__ float unmapf(unsigned u) {
    return __uint_as_float((u & 0x80000000u) ? (u & 0x7FFFFFFFu) : ~u);
}
__device__ __forceinline__ int po2k(float m) {
    m = fmaxf(m, 1e-8f);
    int e; float f = frexpf(m, &e);
    return (f == 0.5f) ? (e - 1) : e;
}
__device__ __forceinline__ float sc(int k)    { return __uint_as_float((unsigned)(k + 120) << 23); }
__device__ __forceinline__ float scinv(int k) { return __uint_as_float((unsigned)(134 - k) << 23); }
__device__ __forceinline__ float fq1(float x, float s, float inv) {
    float q = rintf(x * inv);
    q = fminf(fmaxf(q, -128.0f), 127.0f);
    return q * s;
}
__device__ __forceinline__ float sigm(float x) { return 1.0f / (1.0f + expf(-x)); }
__device__ __forceinline__ unsigned warp_max_u(unsigned v) {
#pragma unroll
    for (int o = 16; o; o >>= 1) v = max(v, __shfl_xor_sync(0xffffffffu, v, o));
    return v;
}
__device__ __forceinline__ void red_max_rlx(unsigned* p, unsigned v) {
    asm volatile("red.relaxed.gpu.max.u32 [%0],%1;" :: "l"(p), "r"(v) : "memory");
}
__device__ __forceinline__ unsigned atom_add_acqrel(unsigned* p, unsigned v) {
    unsigned old;
    asm volatile("atom.acq_rel.gpu.add.u32 %0,[%1],%2;" : "=r"(old) : "l"(p), "r"(v) : "memory");
    return old;
}
__device__ __forceinline__ unsigned ld_acq(const unsigned* p) {
    unsigned v; asm volatile("ld.acquire.gpu.u32 %0,[%1];" : "=r"(v) : "l"(p) : "memory"); return v;
}
__device__ __forceinline__ unsigned ld_rlx(const unsigned* p) {
    unsigned v; asm volatile("ld.relaxed.gpu.u32 %0,[%1];" : "=r"(v) : "l"(p) : "memory"); return v;
}

// fallback grid round (rare path), R6-proven protocol
__device__ __forceinline__ unsigned grid_bar(unsigned* cell0, unsigned myv, int nc,
                                             unsigned tgt, int lane) {
    if (lane < nc) red_max_rlx(cell0 + lane * CSTRIDE, myv);
    __syncwarp();
    unsigned last = 0;
    if (lane == 0) last = (atom_add_acqrel(&g_ctr0[0], 1u) == tgt - 1u) ? 1u : 0u;
    last = __shfl_sync(0xffffffffu, last, 0);
    if (!last) { while (ld_acq(&g_ctr0[0]) < tgt) { } }
    __syncwarp();
    return (lane < nc) ? ld_rlx(cell0 + lane * CSTRIDE) : 0u;
}

__global__ void __launch_bounds__(NT, 1) qlstm_main(
    const float* __restrict__ x,
    const float* __restrict__ Wih,
    const float* __restrict__ Whh,
    float* __restrict__ out)
{
    __shared__ __align__(16) float sh_h[BPB * NH];
    __shared__ __align__(16) float sh_x[BPB * NI];
    __shared__ float               sh_act[NG * BPB];
    __shared__ unsigned            sh_red[12];
    __shared__ int                 sh_k[8];    // true: 0:k1 1-4:ka 5:k3 6:kh 7:code
    __shared__ int                 sh_kp[8];   // predictions

    const int tid  = threadIdx.x;
    const int bid  = blockIdx.x;
    const int g    = tid / BPB;
    const int b    = tid % BPB;
    const int gr   = tid / 160;          // warp-uniform gate group
    const int lane = tid & 31;
    const int wid  = tid >> 5;
    const bool isC = (wid >= 5 && wid < 10);          // phase-C warps
    const int  cj  = (tid - 160) / BPB;               // hidden index (isC)
    const int  cb  = (tid - 160) % BPB;               // batch (isC); valid when isC

    if (tid < 12) sh_red[tid] = 0u;
    if (tid < 8)  { sh_kp[tid] = 99; sh_k[tid] = 0; } // garbage -> full miss at t=0
    if (tid < BPB * NH) sh_h[tid] = 0.0f;
    __syncthreads();

    // ---- weight scale (block-local, once) ----
    {
        float wm = 0.0f;
        for (int k = tid; k < NG * NI; k += NT) wm = fmaxf(wm, fabsf(Wih[k]));
        for (int k = tid; k < NG * NH; k += NT) wm = fmaxf(wm, fabsf(Whh[k]));
        unsigned u = warp_max_u(__float_as_uint(wm));
        if (lane == 0) atomicMax(&sh_red[11], u);
        __syncthreads();
    }
    int kw = po2k(__uint_as_float(sh_red[11]));
    float ws = sc(kw), wsi = scinv(kw);
    __syncthreads();
    if (tid == 0) sh_red[11] = 0u;
    __syncthreads();

    float wi[NI], wh[NH];
#pragma unroll
    for (int i2 = 0; i2 < NI; i2++) wi[i2] = fq1(Wih[g * NI + i2], ws, wsi);
#pragma unroll
    for (int j2 = 0; j2 < NH; j2++) wh[j2] = fq1(Whh[g * NH + j2], ws, wsi);

    float    c = 0.0f, c_prev = 0.0f;    // phase-C state (isC threads)
    float    tc = 0.0f, oq = 0.0f, hp = 0.0f;
    unsigned nbar = 0;

    const int sq  = tid - 560;           // warps 17-19 stage x
    const int sxb = (sq >= 0) ? sq / NI : 0;
    const int sxi = (sq >= 0) ? sq % NI : 0;
    float xr = 0.0f;
    if (sq >= 0) {
        sh_x[sq] = x[((size_t)(bid * BPB + sxb) * T_STEPS + 0) * NI + sxi];
        xr       = x[((size_t)(bid * BPB + sxb) * T_STEPS + 1) * NI + sxi];
    }
    __syncthreads();

    for (int t = 0; t < T_STEPS; ++t) {
        const int k1p = sh_kp[0], kap = sh_kp[1 + gr], k3p = sh_kp[5], khp = sh_kp[6];
        unsigned* cbase = &g_cells[(size_t)t * NCELL * CSTRIDE];

        // ===== phase B (all warps): pre + gate extrema + speculative act =====
        float p0 = 0.0f, p1 = 0.0f;
        {
            const float2* px = reinterpret_cast<const float2*>(&sh_x[b * NI]);
            const float2* ph = reinterpret_cast<const float2*>(&sh_h[b * NH]);
#pragma unroll
            for (int j = 0; j < NI / 2; j++) {
                float2 v = px[j];
                p0 = fmaf(v.x, wi[2 * j], p0); p1 = fmaf(v.y, wi[2 * j + 1], p1);
            }
#pragma unroll
            for (int j = 0; j < NH / 2; j++) {
                float2 v = ph[j];
                p0 = fmaf(v.x, wh[2 * j], p0); p1 = fmaf(v.y, wh[2 * j + 1], p1);
            }
        }
        float pre = p0 + p1;
        unsigned kp = warp_max_u(mapf(pre));
        unsigned kn = warp_max_u(mapf(-pre));
        if (lane == 0) { atomicMax(&sh_red[gr], kp); atomicMax(&sh_red[4 + gr], kn); }
        {
            float gq  = fq1(pre, sc(k1p), scinv(k1p));
            float act = (gr == 2) ? tanhf(gq) : sigm(gq);
            sh_act[tid] = fq1(act, sc(kap), scinv(kap));
        }
        __syncthreads();                                        // S1

        if (wid == 0) {
            // ---- dedicated barrier warp: gather + fire cells 0-5 (overlaps C)
            unsigned v = (lane < 8) ? sh_red[lane] : 0u;
            __syncwarp();
            if (lane < 8) sh_red[lane] = 0u;
            unsigned n0 = __shfl_sync(0xffffffffu, v, 4);
            unsigned n1 = __shfl_sync(0xffffffffu, v, 5);
            unsigned n2 = __shfl_sync(0xffffffffu, v, 6);
            unsigned n3 = __shfl_sync(0xffffffffu, v, 7);
            unsigned myv = v;
            if (lane == 4) myv = n2;                            // max(-pre) tanh group
            if (lane == 5) myv = max(max(n0, n1), max(n2, n3)); // global max(-pre)
            if (lane < 6) red_max_rlx(cbase + lane * CSTRIDE, myv);
        } else if (isC) {
            // ---- phase C (warps 5-9): c update, tanh, speculative h_pre & h
            float iq = sh_act[tid - 160], ff = sh_act[tid];
            float gg = sh_act[tid + 160]; oq = sh_act[tid + 320];
            c_prev = c;
            c  = ff * c + iq * gg;
            tc = tanhf(c);
            hp = oq * fq1(tc, sc(k3p), scinv(k3p));
            float hq = fq1(hp, sc(khp), scinv(khp));            // speculative h
            sh_h[cb * NH + cj] = hq;
            out[((size_t)(bid * BPB + cb) * T_STEPS + t) * NH + cj] = hq;
            unsigned a1 = warp_max_u(__float_as_uint(fabsf(tc)));
            unsigned a2 = warp_max_u(__float_as_uint(fabsf(hp)));
            if (lane == 0) { atomicMax(&sh_red[8], a1); atomicMax(&sh_red[9], a2); }
        } else if (sq >= 0) {
            if (t + 1 < T_STEPS) sh_x[sq] = xr;                 // publish x(t+1)
            if (t + 2 < T_STEPS)
                xr = x[((size_t)(bid * BPB + sxb) * T_STEPS + (t + 2)) * NI + sxi];
        }

        if (wid == 0 || isC)
            asm volatile("bar.sync 1, 192;" ::: "memory");      // {w0, w5-9}

        // ===== warp 0: fire cells 6-7 + counter, poll, read, verify =====
        if (wid == 0) {
            unsigned v89 = (lane < 2) ? sh_red[8 + lane] : 0u;
            __syncwarp();
            if (lane < 2) sh_red[8 + lane] = 0u;
            unsigned t8 = __shfl_sync(0xffffffffu, v89, 0);
            unsigned t9 = __shfl_sync(0xffffffffu, v89, 1);
            if (lane == 6) red_max_rlx(cbase + 6 * CSTRIDE, t8);
            if (lane == 7) red_max_rlx(cbase + 7 * CSTRIDE, t9);
            __syncwarp();
            nbar++;
            unsigned tgt = nbar * GB, last = 0;
            if (lane == 0) last = (atom_add_acqrel(&g_ctr0[0], 1u) == tgt - 1u) ? 1u : 0u;
            last = __shfl_sync(0xffffffffu, last, 0);
            if (!last) { while (ld_acq(&g_ctr0[0]) < tgt) { } }
            __syncwarp();
            unsigned cv = (lane < 8) ? ld_rlx(cbase + lane * CSTRIDE) : 0u;

            unsigned kk = (lane < 4 || lane == 5) ? cv : 0u;
            kk = max(kk, __shfl_xor_sync(0xffffffffu, kk, 4));
            kk = max(kk, __shfl_xor_sync(0xffffffffu, kk, 2));
            kk = max(kk, __shfl_xor_sync(0xffffffffu, kk, 1));
            int k1 = po2k(unmapf(kk));
            float s1 = sc(k1), v1 = scinv(k1);
            float mng = unmapf(__shfl_sync(0xffffffffu, cv, 4));
            float myp = unmapf(cv);
            float a;
            if (lane == 2) {
                float q1 = fq1(myp, s1, v1), q2 = fq1(-mng, s1, v1);
                a = tanhf(fmaxf(q1, -q2));
            } else {
                a = sigm(fq1(myp, s1, v1));
            }
            int ka  = po2k(fabsf(a));
            int k3t = po2k(__uint_as_float(__shfl_sync(0xffffffffu, cv, 6)));
            int kht = po2k(__uint_as_float(__shfl_sync(0xffffffffu, cv, 7)));
            bool okl = (lane < 4) ? (ka == sh_kp[1 + lane]) : true;
            unsigned bm = __ballot_sync(0xffffffffu, okl);
            int hit1 = (((bm & 0xFu) == 0xFu) && (k1 == sh_kp[0])) ? 1 : 0;
            int hit3 = (k3t == sh_kp[5]) ? 1 : 0;
            int hith = (kht == sh_kp[6]) ? 1 : 0;
            int code = hit1 ? (hit3 ? (hith ? 0 : 1) : 2) : 3;
            if (lane < 4) { sh_k[1 + lane] = ka; sh_kp[1 + lane] = ka; }
            if (lane == 0) {
                sh_k[0] = k1; sh_kp[0] = k1;
                if (hit1) { sh_k[5] = k3t; sh_kp[5] = k3t; }
                if (hit1 && hit3) { sh_k[6] = kht; sh_kp[6] = kht; }
                sh_k[7] = code;
            }
        }
        __syncthreads();                                        // S3

        const int code = sh_k[7];
        if (code == 0) continue;                                // full hit: done

        if (code == 1) {
            // kh miss only (cell 7 exact): local rewrite
            if (isC) {
                float sh_ = sc(sh_k[6]), vh_ = scinv(sh_k[6]);
                float hq = fq1(hp, sh_, vh_);
                sh_h[cb * NH + cj] = hq;
                out[((size_t)(bid * BPB + cb) * T_STEPS + t) * NH + cj] = hq;
            }
            __syncthreads();
        } else if (code == 2) {
            // k3 miss (tc exact): recompute hp with true k3, one round for kh
            if (isC) {
                float s3 = sc(sh_k[5]), v3 = scinv(sh_k[5]);
                hp = oq * fq1(tc, s3, v3);
                unsigned a2 = warp_max_u(__float_as_uint(fabsf(hp)));
                if (lane == 0) atomicMax(&sh_red[10], a2);
            }
            __syncthreads();
            if (wid == 0) {
                unsigned v = (lane == 0) ? sh_red[10] : 0u;
                __syncwarp();
                if (lane == 0) sh_red[10] = 0u;
                nbar++;
                unsigned cv = grid_bar(cbase + 8 * CSTRIDE, v, 1, nbar * GB, lane);
                if (lane == 0) { sh_k[6] = po2k(__uint_as_float(cv)); sh_kp[6] = sh_k[6]; }
            }
            __syncthreads();
            if (isC) {
                float sh_ = sc(sh_k[6]), vh_ = scinv(sh_k[6]);
                float hq = fq1(hp, sh_, vh_);
                sh_h[cb * NH + cj] = hq;
                out[((size_t)(bid * BPB + cb) * T_STEPS + t) * NH + cj] = hq;
            }
            __syncthreads();
        } else {
            // full miss: replay from exact pre / c_prev with true k1/ka
            {
                int k1 = sh_k[0], kat = sh_k[1 + gr];
                float gq  = fq1(pre, sc(k1), scinv(k1));
                float act = (gr == 2) ? tanhf(gq) : sigm(gq);
                sh_act[tid] = fq1(act, sc(kat), scinv(kat));
            }
            __syncthreads();
            int k3g = sh_kp[5];
            if (isC) {
                float iq = sh_act[tid - 160], ff = sh_act[tid];
                float gg = sh_act[tid + 160]; oq = sh_act[tid + 320];
                c  = ff * c_prev + iq * gg;
                tc = tanhf(c);
                hp = oq * fq1(tc, sc(k3g), scinv(k3g));
                unsigned a1 = warp_max_u(__float_as_uint(fabsf(tc)));
                unsigned a2 = warp_max_u(__float_as_uint(fabsf(hp)));
                if (lane == 0) { atomicMax(&sh_red[10], a1); atomicMax(&sh_red[11], a2); }
            }
            __syncthreads();
            if (wid == 0) {
                unsigned v = (lane < 2) ? sh_red[10 + lane] : 0u;
                __syncwarp();
                if (lane < 2) sh_red[10 + lane] = 0u;
                nbar++;
                unsigned cv = grid_bar(cbase + 9 * CSTRIDE, v, 2, nbar * GB, lane);
                int kx = po2k(__uint_as_float(cv));
                int k3 = __shfl_sync(0xffffffffu, kx, 0);
                int kh = __shfl_sync(0xffffffffu, kx, 1);
                if (lane == 0) {
                    sh_k[5] = k3; sh_kp[5] = k3; sh_k[6] = kh; sh_kp[6] = kh;
                    sh_k[7] = (k3 == k3g) ? 0 : 1;   // retry flag
                }
            }
            __syncthreads();
            if (sh_k[7]) {                           // k3 guess also missed
                if (isC) {
                    float s3 = sc(sh_k[5]), v3 = scinv(sh_k[5]);
                    hp = oq * fq1(tc, s3, v3);
                    unsigned a2 = warp_max_u(__float_as_uint(fabsf(hp)));
                    if (lane == 0) atomicMax(&sh_red[10], a2);
                }
                __syncthreads();
                if (wid == 0) {
                    unsigned v = (lane == 0) ? sh_red[10] : 0u;
                    __syncwarp();
                    if (lane == 0) sh_red[10] = 0u;
                    nbar++;
                    unsigned cv = grid_bar(cbase + 11 * CSTRIDE, v, 1, nbar * GB, lane);
                    if (lane == 0) { sh_k[6] = po2k(__uint_as_float(cv)); sh_kp[6] = sh_k[6]; }
                }
                __syncthreads();
            }
            if (isC) {
                float sh_ = sc(sh_k[6]), vh_ = scinv(sh_k[6]);
                float hq = fq1(hp, sh_, vh_);
                sh_h[cb * NH + cj] = hq;
                out[((size_t)(bid * BPB + cb) * T_STEPS + t) * NH + cj] = hq;
            }
            __syncthreads();
        }
    }
}

extern "C" void kernel_launch(void* const* d_in, const int* in_sizes, int n_in,
                              void* d_out, int out_size) {
    (void)in_sizes; (void)n_in; (void)out_size;
    qlstm_init<<<32, 512>>>();
    qlstm_main<<<GB, NT>>>((const float*)d_in[0],
                           (const float*)d_in[1],
                           (const float*)d_in[2],
                           (float*)d_out);
}